// round 3
// baseline (speedup 1.0000x reference)
#include <cuda_runtime.h>
#include <cstdint>
#include <cstddef>

#define DEV __device__ __forceinline__

static constexpr int BD = 4096, HD = 1024, KD = 2048, ND = 4096;
static constexpr int TM = 256, TN = 128, KC = 32;
static constexpr int NKC = KD / KC;                 // 64 chunks
static constexpr int NSTG = 3;
static constexpr int STG_A = TM * KC * 4;           // 32768
static constexpr int STG_B = TN * KC * 4;           // 16384
static constexpr int STG_BYTES = STG_A + STG_B;     // 49152
static constexpr int SMEM_TOTAL = NSTG * STG_BYTES; // 147456

// fragment-shuffled tf32 copies + ifgo scratch
__device__ __align__(16) float g_Apk[(size_t)BD * KD];
__device__ __align__(16) float g_Bpk[(size_t)ND * KD];
__device__ __align__(16) float g_ifgo[(size_t)BD * ND];

DEV uint32_t smem_u32(const void* p) {
    uint32_t a;
    asm("{ .reg .u64 t; cvta.to.shared.u64 t, %1; cvt.u32.u64 %0, t; }" : "=r"(a) : "l"(p));
    return a;
}
DEV void cpa16(uint32_t d, const void* s) {
    asm volatile("cp.async.cg.shared.global [%0], [%1], 16;" :: "r"(d), "l"(s) : "memory");
}
DEV void cpa8(uint32_t d, const void* s) {
    asm volatile("cp.async.ca.shared.global [%0], [%1], 8;" :: "r"(d), "l"(s) : "memory");
}
DEV void cpa_commit() { asm volatile("cp.async.commit_group;" ::: "memory"); }
template <int N> DEV void cpa_wait() { asm volatile("cp.async.wait_group %0;" :: "n"(N) : "memory"); }

DEV float tf32r(float x) { float y; asm("cvt.rna.tf32.f32 %0, %1;" : "=f"(y) : "f"(x)); return y; }
DEV float sigf(float x)  { return 1.0f / (1.0f + __expf(-x)); }
DEV float tanhf_(float x) {
    float e = __expf(-2.0f * fabsf(x));
    return copysignf((1.0f - e) / (1.0f + e), x);
}

#define LDS128(v, a) asm volatile("ld.shared.v4.b32 {%0,%1,%2,%3}, [%4];" \
    : "=r"((v)[0]), "=r"((v)[1]), "=r"((v)[2]), "=r"((v)[3]) : "r"(a))
#define LDS64(v, a) asm volatile("ld.shared.v2.b32 {%0,%1}, [%2];" \
    : "=r"((v)[0]), "=r"((v)[1]) : "r"(a))
#define MMA8(c, a, b) asm volatile( \
    "mma.sync.aligned.m16n8k8.row.col.f32.tf32.tf32.f32 " \
    "{%0,%1,%2,%3}, {%4,%5,%6,%7}, {%8,%9}, {%0,%1,%2,%3};" \
    : "+f"((c)[0]), "+f"((c)[1]), "+f"((c)[2]), "+f"((c)[3]) \
    : "r"((a)[0]), "r"((a)[1]), "r"((a)[2]), "r"((a)[3]), "r"((b)[0]), "r"((b)[1]))

// ---- pack A: g_Apk[((mb*256+k8)*32+lane)*4+slot] = tf32([x|h][m][k]) in mma frag order ----
// a0:r=t/4,c=t%4  a1:r+8  a2:c+4  a3:both   (16x8 tile per (mb,k8))
__global__ void __launch_bounds__(256) pack_a(const float* __restrict__ x,
                                              const float* __restrict__ h) {
    size_t tid = (size_t)blockIdx.x * 256 + threadIdx.x;     // BD*KD elems
    int slot = tid & 3;
    int lane = (tid >> 2) & 31;
    int k8   = (tid >> 7) & 255;
    int mb   = (int)(tid >> 15);
    int r = (lane >> 2) + ((slot & 1) << 3);
    int c = (lane & 3) + ((slot & 2) << 1);
    int m = mb * 16 + r, k = k8 * 8 + c;
    float v = (k < HD) ? x[(size_t)m * HD + k] : h[(size_t)m * HD + (k - HD)];
    g_Apk[tid] = tf32r(v);
}

// ---- pack B: g_Bpk[((nb*256+k8)*32+lane)*2+slot] = tf32(W[k][n]) in mma frag order ----
// b0: k=t%4, n=t/4 ; b1: k=t%4+4   (8x8 tile per (nb,k8))
__global__ void __launch_bounds__(256) pack_b(const float* __restrict__ wi,
                                              const float* __restrict__ wh) {
    size_t tid = (size_t)blockIdx.x * 256 + threadIdx.x;     // ND*KD elems
    int slot = tid & 1;
    int lane = (tid >> 1) & 31;
    int k8   = (tid >> 6) & 255;
    int nb   = (int)(tid >> 14);
    int n = nb * 8 + (lane >> 2);
    int k = k8 * 8 + (lane & 3) + 4 * slot;
    float v = (k < HD) ? wi[(size_t)k * ND + n] : wh[(size_t)(k - HD) * ND + n];
    g_Bpk[tid] = tf32r(v);
}

// ---- GEMM: ifgo[256x128 tile] += Apk @ Bpk^T via mma.sync tf32 ----
__global__ void __launch_bounds__(512, 1) gemm_tf32() {
    extern __shared__ char smem[];
    const uint32_t sb = smem_u32(smem);
    const int tid = threadIdx.x, wid = tid >> 5, lane = tid & 31;
    const int wm = wid >> 2, wn = wid & 3;               // 4x4 warp grid
    const int m0 = blockIdx.y * TM, n0 = blockIdx.x * TN;
    const int mb0 = m0 >> 4, nb0 = n0 >> 3;

    float acc[4][4][4];
#pragma unroll
    for (int i = 0; i < 4; ++i)
#pragma unroll
        for (int j = 0; j < 4; ++j)
#pragma unroll
            for (int u = 0; u < 4; ++u) acc[i][j][u] = 0.f;

    // loader lambda-ish: per stage s, chunk kc: 2048 x 16B (A) + 2048 x 8B (B)
    auto issue = [&](int s, int kc) {
        const uint32_t SA = sb + s * STG_BYTES, SB = SA + STG_A;
#pragma unroll
        for (int i = 0; i < 4; ++i) {
            int u = tid + i * 512;
            int mb = u >> 7, j = (u >> 5) & 3, ln = u & 31;
            const float* src = g_Apk + (((size_t)(mb0 + mb) * 256 + kc * 4 + j) * 32 + ln) * 4;
            cpa16(SA + u * 16, src);
        }
#pragma unroll
        for (int i = 0; i < 4; ++i) {
            int u = tid + i * 512;
            int nb = u >> 7, j = (u >> 5) & 3, ln = u & 31;
            const float* src = g_Bpk + (((size_t)(nb0 + nb) * 256 + kc * 4 + j) * 32 + ln) * 2;
            cpa8(SB + u * 8, src);
        }
        cpa_commit();
    };

    issue(0, 0);
    issue(1, 1);

    for (int kc = 0; kc < NKC; ++kc) {
        const int s = kc % NSTG;
        cpa_wait<1>();
        __syncthreads();
        const uint32_t SA = sb + s * STG_BYTES, SB = SA + STG_A;
#pragma unroll
        for (int j = 0; j < 4; ++j) {
            uint32_t a[4][4], b[4][2];
#pragma unroll
            for (int im = 0; im < 4; ++im)
                LDS128(a[im], SA + (((wm * 4 + im) * 4 + j) * 32 + lane) * 16);
#pragma unroll
            for (int in = 0; in < 4; ++in)
                LDS64(b[in], SB + (((wn * 4 + in) * 4 + j) * 32 + lane) * 8);
#pragma unroll
            for (int im = 0; im < 4; ++im)
#pragma unroll
                for (int in = 0; in < 4; ++in)
                    MMA8(acc[im][in], a[im], b[in]);
        }
        __syncthreads();
        if (kc + 2 < NKC) issue((kc + 2) % NSTG, kc + 2);
        else cpa_commit();   // keep group count consistent for wait<1>
    }

    // epilogue -> g_ifgo
    const int rbase = m0 + wm * 64 + (lane >> 2);
    const int cbase = n0 + wn * 32 + (lane & 3) * 2;
#pragma unroll
    for (int im = 0; im < 4; ++im)
#pragma unroll
        for (int in = 0; in < 4; ++in) {
            const int r = rbase + im * 16, c = cbase + in * 8;
            *(float2*)(g_ifgo + (size_t)r * ND + c) = make_float2(acc[im][in][0], acc[im][in][1]);
            *(float2*)(g_ifgo + (size_t)(r + 8) * ND + c) = make_float2(acc[im][in][2], acc[im][in][3]);
        }
}

// ---- elementwise LSTM activation ----
__global__ void __launch_bounds__(256) lstm_act(const float* __restrict__ c_t,
                                                const float* __restrict__ b_i,
                                                const float* __restrict__ b_h,
                                                float* __restrict__ out) {
    size_t i = (size_t)blockIdx.x * 256 + threadIdx.x;   // BD*HD/4 groups
    int b = (int)(i >> 8);
    int hc = (int)(i & 255) * 4;
    size_t base = (size_t)b * ND + hc;
    float4 iv = *(const float4*)(g_ifgo + base);
    float4 fv = *(const float4*)(g_ifgo + base + 1024);
    float4 gv = *(const float4*)(g_ifgo + base + 2048);
    float4 ov = *(const float4*)(g_ifgo + base + 3072);
    float4 bii = *(const float4*)(b_i + hc),        bhi = *(const float4*)(b_h + hc);
    float4 bif = *(const float4*)(b_i + 1024 + hc), bhf = *(const float4*)(b_h + 1024 + hc);
    float4 big = *(const float4*)(b_i + 2048 + hc), bhg = *(const float4*)(b_h + 2048 + hc);
    float4 bio = *(const float4*)(b_i + 3072 + hc), bho = *(const float4*)(b_h + 3072 + hc);
    float4 cv = *(const float4*)(c_t + (size_t)b * HD + hc);

    float hn[4], cn[4];
    const float* pi = &iv.x; const float* pf = &fv.x; const float* pg = &gv.x; const float* po = &ov.x;
    const float* pbii = &bii.x; const float* pbhi = &bhi.x;
    const float* pbif = &bif.x; const float* pbhf = &bhf.x;
    const float* pbig = &big.x; const float* pbhg = &bhg.x;
    const float* pbio = &bio.x; const float* pbho = &bho.x;
    const float* pc = &cv.x;
#pragma unroll
    for (int u = 0; u < 4; ++u) {
        float I = sigf(pi[u] + pbii[u] + pbhi[u]);
        float F = sigf(pf[u] + pbif[u] + pbhf[u]);
        float G = tanhf_(pg[u] + pbig[u] + pbhg[u]);
        float O = sigf(po[u] + pbio[u] + pbho[u]);
        cn[u] = F * pc[u] + I * G;
        hn[u] = O * tanhf_(cn[u]);
    }
    *(float4*)(out + (size_t)b * HD + hc) = make_float4(hn[0], hn[1], hn[2], hn[3]);
    *(float4*)(out + (size_t)BD * HD + (size_t)b * HD + hc) = make_float4(cn[0], cn[1], cn[2], cn[3]);
}

extern "C" void kernel_launch(void* const* d_in, const int* in_sizes, int n_in,
                              void* d_out, int out_size) {
    const float* input = (const float*)d_in[0];
    const float* h_t   = (const float*)d_in[1];
    const float* c_t   = (const float*)d_in[2];
    const float* w_i   = (const float*)d_in[3];
    const float* w_h   = (const float*)d_in[4];
    const float* b_i   = (const float*)d_in[5];
    const float* b_h   = (const float*)d_in[6];
    float* out = (float*)d_out;

    cudaFuncSetAttribute(gemm_tf32, cudaFuncAttributeMaxDynamicSharedMemorySize, SMEM_TOTAL);

    pack_a<<<(int)(((size_t)BD * KD) / 256), 256>>>(input, h_t);
    pack_b<<<(int)(((size_t)ND * KD) / 256), 256>>>(w_i, w_h);
    gemm_tf32<<<dim3(ND / TN, BD / TM), 512, SMEM_TOTAL>>>();
    lstm_act<<<(int)(((size_t)BD * HD / 4) / 256), 256>>>(c_t, b_i, b_h, out);
}

// round 4
// speedup vs baseline: 1.0273x; 1.0273x over previous
#include <cuda_runtime.h>
#include <cstdint>
#include <cstddef>

#define DEV __device__ __forceinline__

static constexpr int BD = 4096, HD = 1024, KD = 2048, ND = 4096;
static constexpr int TM = 256, TN = 128, KC = 32;
static constexpr int NKC = KD / KC;                 // 64 chunks
static constexpr int NSTG = 4;
static constexpr int STG_A = TM * KC * 4;           // 32768
static constexpr int STG_B = TN * KC * 4;           // 16384
static constexpr int STG_BYTES = STG_A + STG_B;     // 49152
static constexpr int SM_BIAS = NSTG * STG_BYTES;    // 196608
static constexpr int SMEM_TOTAL = SM_BIAS + 128 * 4;

__device__ __align__(16) float g_Apk[(size_t)BD * KD];
__device__ __align__(16) float g_Bpk[(size_t)ND * KD];

DEV uint32_t smem_u32(const void* p) {
    uint32_t a;
    asm("{ .reg .u64 t; cvta.to.shared.u64 t, %1; cvt.u32.u64 %0, t; }" : "=r"(a) : "l"(p));
    return a;
}
DEV void cpa16(uint32_t d, const void* s) {
    asm volatile("cp.async.cg.shared.global [%0], [%1], 16;" :: "r"(d), "l"(s) : "memory");
}
DEV void cpa8(uint32_t d, const void* s) {
    asm volatile("cp.async.ca.shared.global [%0], [%1], 8;" :: "r"(d), "l"(s) : "memory");
}
DEV void cpa_commit() { asm volatile("cp.async.commit_group;" ::: "memory"); }
template <int N> DEV void cpa_wait() { asm volatile("cp.async.wait_group %0;" :: "n"(N) : "memory"); }

DEV float tf32r(float x) { float y; asm("cvt.rna.tf32.f32 %0, %1;" : "=f"(y) : "f"(x)); return y; }
DEV float sigf(float x)  { return 1.0f / (1.0f + __expf(-x)); }
DEV float tanhf_(float x) {
    float e = __expf(-2.0f * fabsf(x));
    return copysignf((1.0f - e) / (1.0f + e), x);
}

#define LDS128(v, a) asm volatile("ld.shared.v4.b32 {%0,%1,%2,%3}, [%4];" \
    : "=r"((v)[0]), "=r"((v)[1]), "=r"((v)[2]), "=r"((v)[3]) : "r"(a))
#define LDS64(v, a) asm volatile("ld.shared.v2.b32 {%0,%1}, [%2];" \
    : "=r"((v)[0]), "=r"((v)[1]) : "r"(a))
#define MMA8(c, a, b) asm volatile( \
    "mma.sync.aligned.m16n8k8.row.col.f32.tf32.tf32.f32 " \
    "{%0,%1,%2,%3}, {%4,%5,%6,%7}, {%8,%9}, {%0,%1,%2,%3};" \
    : "+f"((c)[0]), "+f"((c)[1]), "+f"((c)[2]), "+f"((c)[3]) \
    : "r"((a)[0]), "r"((a)[1]), "r"((a)[2]), "r"((a)[3]), "r"((b)[0]), "r"((b)[1]))

// ---- pack A: mma-fragment-ordered tf32 [x|h] (identical to validated R2) ----
__global__ void __launch_bounds__(256) pack_a(const float* __restrict__ x,
                                              const float* __restrict__ h) {
    size_t tid = (size_t)blockIdx.x * 256 + threadIdx.x;     // BD*KD elems
    int slot = tid & 3;
    int lane = (tid >> 2) & 31;
    int k8   = (tid >> 7) & 255;
    int mb   = (int)(tid >> 15);
    int r = (lane >> 2) + ((slot & 1) << 3);
    int c = (lane & 3) + ((slot & 2) << 1);
    int m = mb * 16 + r, k = k8 * 8 + c;
    float v = (k < HD) ? x[(size_t)m * HD + k] : h[(size_t)m * HD + (k - HD)];
    g_Apk[tid] = tf32r(v);
}

// ---- pack B: fragment-ordered, GATE-INTERLEAVED columns ----
// logical GEMM col n' = t*128 + w*32 + gate*8 + u  <=>  orig col = gate*1024 + t*32 + w*8 + u
// nb' = n'>>3 = t*16 + w*4 + gate
__global__ void __launch_bounds__(256) pack_b(const float* __restrict__ wi,
                                              const float* __restrict__ wh) {
    size_t tid = (size_t)blockIdx.x * 256 + threadIdx.x;     // ND*KD elems
    int slot = tid & 1;
    int lane = (tid >> 1) & 31;
    int k8   = (tid >> 6) & 255;
    int nbp  = (int)(tid >> 14);             // permuted 8-col group, 0..511
    int gate = nbp & 3, w = (nbp >> 2) & 3, t = nbp >> 4;
    int n = gate * 1024 + t * 32 + w * 8 + (lane >> 2);
    int k = k8 * 8 + (lane & 3) + 4 * slot;
    float v = (k < HD) ? wi[(size_t)k * ND + n] : wh[(size_t)(k - HD) * ND + n];
    g_Bpk[tid] = tf32r(v);
}

// ---- fused GEMM (256x128 tile) + LSTM activation epilogue ----
__global__ void __launch_bounds__(512, 1) gemm_lstm(const float* __restrict__ c_t,
                                                    const float* __restrict__ b_i,
                                                    const float* __restrict__ b_h,
                                                    float* __restrict__ out) {
    extern __shared__ char smem[];
    const uint32_t sb = smem_u32(smem);
    float* bias_s = (float*)(smem + SM_BIAS);      // [4 gates][32 hcols]
    const int tid = threadIdx.x, wid = tid >> 5, lane = tid & 31;
    const int wm = wid >> 2, wn = wid & 3;         // 4x4 warp grid
    const int m0 = blockIdx.y * TM;
    const int bx = blockIdx.x;                     // n0 = bx*128, hcol block = bx*32
    const int mb0 = m0 >> 4, nb0 = bx * 16;

    if (tid < 128) {
        int gate = tid >> 5, hl = tid & 31, col = gate * 1024 + bx * 32 + hl;
        bias_s[tid] = b_i[col] + b_h[col];
    }

    float acc[4][4][4];
#pragma unroll
    for (int i = 0; i < 4; ++i)
#pragma unroll
        for (int j = 0; j < 4; ++j)
#pragma unroll
            for (int u = 0; u < 4; ++u) acc[i][j][u] = 0.f;

    auto issue = [&](int s, int kc) {
        const uint32_t SA = sb + s * STG_BYTES, SB = SA + STG_A;
#pragma unroll
        for (int i = 0; i < 4; ++i) {
            int u = tid + i * 512;
            int mb = u >> 7, j = (u >> 5) & 3, ln = u & 31;
            cpa16(SA + u * 16,
                  g_Apk + (((size_t)(mb0 + mb) * 256 + kc * 4 + j) * 32 + ln) * 4);
        }
#pragma unroll
        for (int i = 0; i < 4; ++i) {
            int u = tid + i * 512;
            int nb = u >> 7, j = (u >> 5) & 3, ln = u & 31;
            cpa8(SB + u * 8,
                 g_Bpk + (((size_t)(nb0 + nb) * 256 + kc * 4 + j) * 32 + ln) * 2);
        }
        cpa_commit();
    };

    issue(0, 0);
    issue(1, 1);
    issue(2, 2);

    for (int kc = 0; kc < NKC; ++kc) {
        const int s = kc & (NSTG - 1);
        cpa_wait<2>();
        __syncthreads();                 // single barrier per chunk
        if (kc + 3 < NKC) issue((kc + 3) & (NSTG - 1), kc + 3);
        else cpa_commit();               // keep group arithmetic for wait<2>
        const uint32_t SA = sb + s * STG_BYTES, SB = SA + STG_A;
#pragma unroll
        for (int j = 0; j < 4; ++j) {
            uint32_t a[4][4], b[4][2];
#pragma unroll
            for (int im = 0; im < 4; ++im)
                LDS128(a[im], SA + (((wm * 4 + im) * 4 + j) * 32 + lane) * 16);
#pragma unroll
            for (int in = 0; in < 4; ++in)
                LDS64(b[in], SB + (((wn * 4 + in) * 4 + j) * 32 + lane) * 8);
#pragma unroll
            for (int im = 0; im < 4; ++im)
#pragma unroll
                for (int in = 0; in < 4; ++in)
                    MMA8(acc[im][in], a[im], b[in]);
        }
    }

    // ---- fused epilogue: in = gate; each thread holds i,f,g,o for 2 hcols x 8 rows ----
    const int hl = wn * 8 + (lane & 3) * 2;        // 0..31 within hcol block
    const int hc = bx * 32 + hl;                   // global hidden col
    const int rb = m0 + wm * 64 + (lane >> 2);
    float bI0 = bias_s[hl],      bI1 = bias_s[hl + 1];
    float bF0 = bias_s[32 + hl], bF1 = bias_s[33 + hl];
    float bG0 = bias_s[64 + hl], bG1 = bias_s[65 + hl];
    float bO0 = bias_s[96 + hl], bO1 = bias_s[97 + hl];
#pragma unroll
    for (int im = 0; im < 4; ++im)
#pragma unroll
        for (int half = 0; half < 2; ++half) {
            const int r = rb + im * 16 + half * 8;
            const int q = half * 2;
            float2 cv = *(const float2*)(c_t + (size_t)r * HD + hc);
            float I0 = sigf(acc[im][0][q] + bI0),     I1 = sigf(acc[im][0][q + 1] + bI1);
            float F0 = sigf(acc[im][1][q] + bF0),     F1 = sigf(acc[im][1][q + 1] + bF1);
            float G0 = tanhf_(acc[im][2][q] + bG0),   G1 = tanhf_(acc[im][2][q + 1] + bG1);
            float O0 = sigf(acc[im][3][q] + bO0),     O1 = sigf(acc[im][3][q + 1] + bO1);
            float cn0 = F0 * cv.x + I0 * G0,          cn1 = F1 * cv.y + I1 * G1;
            float hn0 = O0 * tanhf_(cn0),             hn1 = O1 * tanhf_(cn1);
            *(float2*)(out + (size_t)r * HD + hc) = make_float2(hn0, hn1);
            *(float2*)(out + (size_t)BD * HD + (size_t)r * HD + hc) = make_float2(cn0, cn1);
        }
}

extern "C" void kernel_launch(void* const* d_in, const int* in_sizes, int n_in,
                              void* d_out, int out_size) {
    const float* input = (const float*)d_in[0];
    const float* h_t   = (const float*)d_in[1];
    const float* c_t   = (const float*)d_in[2];
    const float* w_i   = (const float*)d_in[3];
    const float* w_h   = (const float*)d_in[4];
    const float* b_i   = (const float*)d_in[5];
    const float* b_h   = (const float*)d_in[6];
    float* out = (float*)d_out;

    cudaFuncSetAttribute(gemm_lstm, cudaFuncAttributeMaxDynamicSharedMemorySize, SMEM_TOTAL);

    pack_a<<<(int)(((size_t)BD * KD) / 256), 256>>>(input, h_t);
    pack_b<<<(int)(((size_t)ND * KD) / 256), 256>>>(w_i, w_h);
    gemm_lstm<<<dim3(ND / TN, BD / TM), 512, SMEM_TOTAL>>>(c_t, b_i, b_h, out);
}

// round 5
// speedup vs baseline: 2.2440x; 2.1843x over previous
#include <cuda_runtime.h>
#include <cuda_fp16.h>
#include <cstdint>
#include <cstddef>

#define DEV __device__ __forceinline__

static constexpr int BD = 4096, HD = 1024, KD = 2048, ND = 4096;
static constexpr int TM = 256, TN = 128, KC = 64;
static constexpr int NKC = KD / KC;                  // 32 chunks
static constexpr int NSTG = 4;
static constexpr int STG_A = TM * KC * 2;            // 32768
static constexpr int STG_B = TN * KC * 2;            // 16384
static constexpr int STG_BYTES = STG_A + STG_B;      // 49152
static constexpr int SM_BIAS = NSTG * STG_BYTES;     // 196608
static constexpr int SMEM_TOTAL = SM_BIAS + 128 * 4;

__device__ __align__(16) __half g_Apk[(size_t)BD * KD];   // 16 MB, frag-ordered
__device__ __align__(16) __half g_Bpk[(size_t)ND * KD];   // 16 MB, frag-ordered + gate-interleaved

DEV uint32_t smem_u32(const void* p) {
    uint32_t a;
    asm("{ .reg .u64 t; cvta.to.shared.u64 t, %1; cvt.u32.u64 %0, t; }" : "=r"(a) : "l"(p));
    return a;
}
DEV void cpa16(uint32_t d, const void* s) {
    asm volatile("cp.async.cg.shared.global [%0], [%1], 16;" :: "r"(d), "l"(s) : "memory");
}
DEV void cpa_commit() { asm volatile("cp.async.commit_group;" ::: "memory"); }
template <int N> DEV void cpa_wait() { asm volatile("cp.async.wait_group %0;" :: "n"(N) : "memory"); }

DEV float sigf(float x)  { return 1.0f / (1.0f + __expf(-x)); }
DEV float tanhf_(float x) {
    float e = __expf(-2.0f * fabsf(x));
    return copysignf((1.0f - e) / (1.0f + e), x);
}

#define LDS128(v, a) asm volatile("ld.shared.v4.b32 {%0,%1,%2,%3}, [%4];" \
    : "=r"((v)[0]), "=r"((v)[1]), "=r"((v)[2]), "=r"((v)[3]) : "r"(a))
#define LDS64(v, a) asm volatile("ld.shared.v2.b32 {%0,%1}, [%2];" \
    : "=r"((v)[0]), "=r"((v)[1]) : "r"(a))
#define MMA16(c, a, b) asm volatile( \
    "mma.sync.aligned.m16n8k16.row.col.f32.f16.f16.f32 " \
    "{%0,%1,%2,%3}, {%4,%5,%6,%7}, {%8,%9}, {%0,%1,%2,%3};" \
    : "+f"((c)[0]), "+f"((c)[1]), "+f"((c)[2]), "+f"((c)[3]) \
    : "r"((a)[0]), "r"((a)[1]), "r"((a)[2]), "r"((a)[3]), "r"((b)[0]), "r"((b)[1]))

// ---- pack A: fp16 fragments of [x|h], smem-staged, coalesced both sides ----
// tile (mb, k16): 16 m x 16 k. dst halves: ((mb*128 + k16)*32 + lane)*8 + slot*2 + e
// slot&1 -> row+8 ; slot&2 -> col+8 ; a-row = lane>>2, a-col = (lane&3)*2+e
__global__ void __launch_bounds__(256) pack_a(const float* __restrict__ x,
                                              const float* __restrict__ h) {
    __shared__ float s[16][132];
    const int mb = blockIdx.x >> 4, kb = blockIdx.x & 15;   // kb: 128-col block
    const int t = threadIdx.x;
    const float* base = (kb < 8) ? x + (size_t)mb * 16 * 1024 + kb * 128
                                 : h + (size_t)mb * 16 * 1024 + (kb - 8) * 128;
#pragma unroll
    for (int i = 0; i < 2; ++i) {
        int q = t + i * 256;                 // 512 float4 total
        int row = q >> 5, c4 = q & 31;
        float4 v = *(const float4*)(base + (size_t)row * 1024 + c4 * 4);
        s[row][c4 * 4 + 0] = v.x; s[row][c4 * 4 + 1] = v.y;
        s[row][c4 * 4 + 2] = v.z; s[row][c4 * 4 + 3] = v.w;
    }
    __syncthreads();
    const int j = t >> 5, lane = t & 31;     // j: k16 tile within block (8)
    __half2 hv[4];
#pragma unroll
    for (int slot = 0; slot < 4; ++slot) {
        int r = (lane >> 2) + (slot & 1) * 8;
        int c = (lane & 3) * 2 + (slot & 2) * 4;
        hv[slot] = __floats2half2_rn(s[r][j * 16 + c], s[r][j * 16 + c + 1]);
    }
    size_t idx = ((size_t)(mb * 128 + kb * 8 + j) * 32 + lane) * 8;
    *(uint4*)(g_Apk + idx) = *(uint4*)hv;
}

// ---- pack B: fp16 fragments, gate-interleaved cols, smem-staged ----
// permuted nbp = tt*16 + w*4 + gate ; orig n = gate*1024 + tt*32 + w*8 + u
// tile (nbp, k16): dst halves ((nbp*128 + k16)*32 + lane)*4 ; b-k=(lane&3)*2(+8), b-n=lane>>2
__global__ void __launch_bounds__(256) pack_b(const float* __restrict__ wi,
                                              const float* __restrict__ wh) {
    __shared__ float s[64][36];
    const int b = blockIdx.x;
    const int kb = b & 31, tt = (b >> 5) & 31, gate = b >> 10;
    const int n0 = gate * 1024 + tt * 32, k0 = kb * 64;
    const int t = threadIdx.x;
#pragma unroll
    for (int i = 0; i < 2; ++i) {
        int q = t + i * 256;                 // 512 float4: 64 rows x 8 f4
        int kr = q >> 3, c4 = q & 7;
        int k = k0 + kr;
        const float* src = ((k < HD) ? wi + (size_t)k * ND : wh + (size_t)(k - HD) * ND) + n0;
        float4 v = *(const float4*)(src + c4 * 4);
        s[kr][c4 * 4 + 0] = v.x; s[kr][c4 * 4 + 1] = v.y;
        s[kr][c4 * 4 + 2] = v.z; s[kr][c4 * 4 + 3] = v.w;
    }
    __syncthreads();
#pragma unroll
    for (int i = 0; i < 2; ++i) {
        int u = t + i * 256;                 // 512 units: (w, k16, lane)
        int w = u >> 7, k16 = (u >> 5) & 3, lane = u & 31;
        int nl = w * 8 + (lane >> 2);
        int kk = k16 * 16 + (lane & 3) * 2;
        __half2 p[2];
        p[0] = __floats2half2_rn(s[kk][nl], s[kk + 1][nl]);
        p[1] = __floats2half2_rn(s[kk + 8][nl], s[kk + 9][nl]);
        int nbp = tt * 16 + w * 4 + gate;
        size_t idx = ((size_t)(nbp * 128 + kb * 4 + k16) * 32 + lane) * 4;
        *(uint2*)(g_Bpk + idx) = *(uint2*)p;
    }
}

// ---- fused fp16 GEMM (256x128 tile) + LSTM epilogue ----
__global__ void __launch_bounds__(512, 1) gemm_lstm(const float* __restrict__ c_t,
                                                    const float* __restrict__ b_i,
                                                    const float* __restrict__ b_h,
                                                    float* __restrict__ out) {
    extern __shared__ char smem[];
    const uint32_t sb = smem_u32(smem);
    float* bias_s = (float*)(smem + SM_BIAS);
    const int tid = threadIdx.x, wid = tid >> 5, lane = tid & 31;
    const int wm = wid >> 2, wn = wid & 3;
    const int m0 = blockIdx.y * TM;
    const int bx = blockIdx.x;
    const int mb0 = m0 >> 4, nb0 = bx * 16;

    if (tid < 128) {
        int gate = tid >> 5, hl = tid & 31, col = gate * 1024 + bx * 32 + hl;
        bias_s[tid] = b_i[col] + b_h[col];
    }

    float acc[4][4][4];
#pragma unroll
    for (int i = 0; i < 4; ++i)
#pragma unroll
        for (int j = 0; j < 4; ++j)
#pragma unroll
            for (int u = 0; u < 4; ++u) acc[i][j][u] = 0.f;

    auto issue = [&](int s, int kc) {
        const uint32_t SA = sb + s * STG_BYTES, SB = SA + STG_A;
        // A: 2048 x 16B  (tile (mb, j) -> 32 lanes x 16B)
#pragma unroll
        for (int i = 0; i < 4; ++i) {
            int u = tid + i * 512;
            int mb = u >> 7, j = (u >> 5) & 3, ln = u & 31;
            cpa16(SA + u * 16,
                  g_Apk + ((size_t)((mb0 + mb) * 128 + kc * 4 + j) * 32 + ln) * 8);
        }
        // B: 1024 x 16B  (tile (nb, j) -> 16 x 16B)
#pragma unroll
        for (int i = 0; i < 2; ++i) {
            int u = tid + i * 512;
            int nb = u >> 6, j = (u >> 4) & 3, q = u & 15;
            cpa16(SB + u * 16,
                  g_Bpk + ((size_t)((nb0 + nb) * 128 + kc * 4 + j) * 32) * 4 + q * 8);
        }
        cpa_commit();
    };

    issue(0, 0);
    issue(1, 1);
    issue(2, 2);

    for (int kc = 0; kc < NKC; ++kc) {
        const int s = kc & (NSTG - 1);
        cpa_wait<2>();
        __syncthreads();
        if (kc + 3 < NKC) issue((kc + 3) & (NSTG - 1), kc + 3);
        else cpa_commit();
        const uint32_t SA = sb + s * STG_BYTES, SB = SA + STG_A;
#pragma unroll
        for (int j = 0; j < 4; ++j) {
            uint32_t a[4][4], b[4][2];
#pragma unroll
            for (int im = 0; im < 4; ++im)
                LDS128(a[im], SA + (((wm * 4 + im) * 4 + j) * 32 + lane) * 16);
#pragma unroll
            for (int in = 0; in < 4; ++in)
                LDS64(b[in], SB + (((wn * 4 + in) * 4 + j) * 32 + lane) * 8);
#pragma unroll
            for (int im = 0; im < 4; ++im)
#pragma unroll
                for (int in = 0; in < 4; ++in)
                    MMA16(acc[im][in], a[im], b[in]);
        }
    }

    // ---- fused epilogue (same c-frag layout as m16n8k8): in-index = gate ----
    const int hl = wn * 8 + (lane & 3) * 2;
    const int hc = bx * 32 + hl;
    const int rb = m0 + wm * 64 + (lane >> 2);
    float bI0 = bias_s[hl],      bI1 = bias_s[hl + 1];
    float bF0 = bias_s[32 + hl], bF1 = bias_s[33 + hl];
    float bG0 = bias_s[64 + hl], bG1 = bias_s[65 + hl];
    float bO0 = bias_s[96 + hl], bO1 = bias_s[97 + hl];
#pragma unroll
    for (int im = 0; im < 4; ++im)
#pragma unroll
        for (int half = 0; half < 2; ++half) {
            const int r = rb + im * 16 + half * 8;
            const int q = half * 2;
            float2 cv = *(const float2*)(c_t + (size_t)r * HD + hc);
            float I0 = sigf(acc[im][0][q] + bI0),   I1 = sigf(acc[im][0][q + 1] + bI1);
            float F0 = sigf(acc[im][1][q] + bF0),   F1 = sigf(acc[im][1][q + 1] + bF1);
            float G0 = tanhf_(acc[im][2][q] + bG0), G1 = tanhf_(acc[im][2][q + 1] + bG1);
            float O0 = sigf(acc[im][3][q] + bO0),   O1 = sigf(acc[im][3][q + 1] + bO1);
            float cn0 = F0 * cv.x + I0 * G0,        cn1 = F1 * cv.y + I1 * G1;
            float hn0 = O0 * tanhf_(cn0),           hn1 = O1 * tanhf_(cn1);
            *(float2*)(out + (size_t)r * HD + hc) = make_float2(hn0, hn1);
            *(float2*)(out + (size_t)BD * HD + (size_t)r * HD + hc) = make_float2(cn0, cn1);
        }
}

extern "C" void kernel_launch(void* const* d_in, const int* in_sizes, int n_in,
                              void* d_out, int out_size) {
    const float* input = (const float*)d_in[0];
    const float* h_t   = (const float*)d_in[1];
    const float* c_t   = (const float*)d_in[2];
    const float* w_i   = (const float*)d_in[3];
    const float* w_h   = (const float*)d_in[4];
    const float* b_i   = (const float*)d_in[5];
    const float* b_h   = (const float*)d_in[6];
    float* out = (float*)d_out;

    cudaFuncSetAttribute(gemm_lstm, cudaFuncAttributeMaxDynamicSharedMemorySize, SMEM_TOTAL);

    pack_a<<<256 * 16, 256>>>(input, h_t);
    pack_b<<<4 * 32 * 32, 256>>>(w_i, w_h);
    gemm_lstm<<<dim3(ND / TN, BD / TM), 512, SMEM_TOTAL>>>(c_t, b_i, b_h, out);
}